// round 4
// baseline (speedup 1.0000x reference)
#include <cuda_runtime.h>

#define KNN_K 32
#define CUTOFF 10.0f
#define MAX_MOLS 256

// Per-molecule contiguous ranges in the (sorted) batch array.
__device__ int g_mol_start[MAX_MOLS];
__device__ int g_mol_end[MAX_MOLS];

__global__ void mol_bounds_kernel(const int* __restrict__ batch, int n) {
    int i = blockIdx.x * blockDim.x + threadIdx.x;
    if (i >= n) return;
    int b = batch[i];
    if (i == 0 || batch[i - 1] != b) g_mol_start[b] = i;
    if (i == n - 1 || batch[i + 1] != b) g_mol_end[b] = i + 1;
}

__device__ __forceinline__ unsigned long long u64min(unsigned long long a, unsigned long long b) {
    return a < b ? a : b;
}
__device__ __forceinline__ unsigned long long u64max(unsigned long long a, unsigned long long b) {
    return a < b ? b : a;
}

// Full 32-lane bitonic sort, ascending across lanes (lane l holds l-th smallest).
__device__ __forceinline__ unsigned long long bitonic_sort32(unsigned long long key, int lane) {
    #pragma unroll
    for (int k = 2; k <= 32; k <<= 1) {
        #pragma unroll
        for (int j = k >> 1; j >= 1; j >>= 1) {
            unsigned long long other = __shfl_xor_sync(0xffffffffu, key, j);
            bool up       = ((lane & k) == 0);
            bool lower    = ((lane & j) == 0);
            bool keep_min = (lower == up);
            unsigned long long mn = u64min(key, other);
            unsigned long long mx = u64max(key, other);
            key = keep_min ? mn : mx;
        }
    }
    return key;
}

// held: sorted asc (32 smallest so far). cand: sorted asc. Returns sorted asc
// 32 smallest of the 64. Classic bitonic merge: min(held[l], cand[31-l]) is a
// bitonic sequence holding exactly the 32 smallest; 5-stage merge re-sorts it.
__device__ __forceinline__ unsigned long long merge_keep32(unsigned long long held,
                                                           unsigned long long cand, int lane) {
    unsigned long long rev = __shfl_sync(0xffffffffu, cand, 31 - lane);
    unsigned long long lo = u64min(held, rev);
    #pragma unroll
    for (int j = 16; j >= 1; j >>= 1) {
        unsigned long long other = __shfl_xor_sync(0xffffffffu, lo, j);
        bool keep_min = ((lane & j) == 0);
        unsigned long long mn = u64min(lo, other);
        unsigned long long mx = u64max(lo, other);
        lo = keep_min ? mn : mx;
    }
    return lo;
}

// Key for candidate j = c*32 + lane: (float_bits(masked_dist) << 32) | j.
// All dists are >= 0 so the float bit pattern is monotone as u32; unsigned
// 64-bit compare == (dist asc, index asc) — exactly jax.lax.top_k tie-breaking.
__device__ __forceinline__ unsigned long long chunk_key(
    int c, int lane, int n, int i, int bi,
    float xi, float yi, float zi, float sqni,
    const float* __restrict__ pos, const int* __restrict__ batch)
{
    int j = (c << 5) + lane;
    if (j >= n) return 0xFFFFFFFFFFFFFFFFull;
    float xj = __ldg(pos + 3 * j);
    float yj = __ldg(pos + 3 * j + 1);
    float zj = __ldg(pos + 3 * j + 2);
    int   bj = __ldg(batch + j);
    // Reference's gram-matrix expansion (kept for numerical parity):
    float sqnj = xj * xj + yj * yj + zj * zj;
    float dt   = xi * xj + yi * yj + zi * zj;
    float sq   = sqni + sqnj - 2.0f * dt;
    sq = fmaxf(sq, 0.0f);
    float d = (sq > 0.0f) ? sqrtf(sq) : 0.0f;
    bool masked = (j == i) || (bj != bi) || (d > CUTOFF);
    float v = masked ? CUTOFF : d;
    return ((unsigned long long)__float_as_uint(v) << 32) | (unsigned int)j;
}

// One warp per row i. Exactness argument for the chunk pruning:
// after chunk 0, all 32 held keys are <= (10.0, 31). Every candidate outside
// chunk 0 and outside i's molecule range is masked (cross-batch) with key
// (10.0, j>=32) > every held key, so it can never belong to the true top-32.
// Hence processing chunk 0 plus the molecule's chunks is exact.
__global__ void __launch_bounds__(128)
knn_kernel(const float* __restrict__ pos, const int* __restrict__ batch,
           float* __restrict__ out, int n)
{
    int warp = (blockIdx.x * blockDim.x + threadIdx.x) >> 5;
    int lane = threadIdx.x & 31;
    if (warp >= n) return;
    int i = warp;

    float xi = __ldg(pos + 3 * i);
    float yi = __ldg(pos + 3 * i + 1);
    float zi = __ldg(pos + 3 * i + 2);
    int   bi = __ldg(batch + i);
    float sqni = xi * xi + yi * yi + zi * zi;

    int ms = g_mol_start[bi];
    int me = g_mol_end[bi];

    // Chunk 0 seeds the held list (covers the index-tiebreak "fill" entries).
    unsigned long long held = chunk_key(0, lane, n, i, bi, xi, yi, zi, sqni, pos, batch);
    held = bitonic_sort32(held, lane);

    // Molecule's own chunk range (skip chunk 0 — already processed).
    int cs = ms >> 5;
    int ce = (me - 1) >> 5;
    for (int c = cs; c <= ce; ++c) {
        if (c == 0) continue;
        unsigned long long cand = chunk_key(c, lane, n, i, bi, xi, yi, zi, sqni, pos, batch);
        cand = bitonic_sort32(cand, lane);
        held = merge_keep32(held, cand, lane);
    }

    // Output layout: [edge_index[0] (N*K), edge_index[1] (N*K), edge_weight (N*K)]
    unsigned int nb = (unsigned int)(held & 0xffffffffu);
    float w = __uint_as_float((unsigned int)(held >> 32));
    int NK = n * KNN_K;
    int base = i * KNN_K + lane;
    out[base]          = (float)nb;   // neighbor index
    out[NK + base]     = (float)i;    // source row
    out[2 * NK + base] = w;           // distance weight
}

extern "C" void kernel_launch(void* const* d_in, const int* in_sizes, int n_in,
                              void* d_out, int out_size)
{
    const float* pos   = (const float*)d_in[0];
    const int*   batch = (const int*)d_in[1];
    float*       out   = (float*)d_out;
    int n = in_sizes[1];  // batch has N elements

    mol_bounds_kernel<<<(n + 255) / 256, 256>>>(batch, n);

    int threads = 128;                       // 4 warps/block, 1 warp per row
    int blocks  = (n * 32 + threads - 1) / threads;
    knn_kernel<<<blocks, threads>>>(pos, batch, out, n);
}

// round 6
// speedup vs baseline: 1.3646x; 1.3646x over previous
#include <cuda_runtime.h>

#define KNN_K 32
#define CUTOFF 10.0f

// Optimized compare-exchange: conditional take instead of min/max+select.
// On equal keys take=false when keep_min (keeps own) — equal u64 keys are
// identical entries (key embeds the index), so either choice is correct.
__device__ __forceinline__ void ce_swap(unsigned long long& key,
                                        unsigned long long other, bool keep_min) {
    bool take = (other < key) == keep_min;
    if (take) key = other;
}

// Full 32-lane bitonic sort. ASC=true: lane l holds l-th smallest.
// ASC=false: descending.
template <bool ASC>
__device__ __forceinline__ unsigned long long bitonic_sort32(unsigned long long key, int lane) {
    #pragma unroll
    for (int k = 2; k <= 32; k <<= 1) {
        #pragma unroll
        for (int j = k >> 1; j >= 1; j >>= 1) {
            unsigned long long other = __shfl_xor_sync(0xffffffffu, key, j);
            bool keep_min = (((lane & k) == 0) == ((lane & j) == 0));
            if (!ASC) keep_min = !keep_min;
            ce_swap(key, other, keep_min);
        }
    }
    return key;
}

// held: sorted asc (32 smallest so far). cand_desc: sorted DESCENDING.
// min(held[l], cand_desc[l]) == min(held[l], cand_asc[31-l]) — the classic
// bitonic keep-32 without the reverse shuffle; 5-stage merge re-sorts asc.
__device__ __forceinline__ unsigned long long merge_keep32(unsigned long long held,
                                                           unsigned long long cand_desc,
                                                           int lane) {
    unsigned long long lo = (held < cand_desc) ? held : cand_desc;
    #pragma unroll
    for (int j = 16; j >= 1; j >>= 1) {
        unsigned long long other = __shfl_xor_sync(0xffffffffu, lo, j);
        ce_swap(lo, other, (lane & j) == 0);
    }
    return lo;
}

// Key for candidate j = c*32 + lane: (float_bits(masked_dist) << 32) | j.
// Dists >= 0 so float bits are u32-monotone; u64 compare == (dist asc, idx asc)
// — exactly jax.lax.top_k tie-breaking. Cross-batch mask uses [ms, me) range
// (batch is sorted) — no batch[] load needed per candidate.
__device__ __forceinline__ unsigned long long chunk_key(
    int c, int lane, int n, int i, int ms, int me,
    float xi, float yi, float zi, float sqni, const float* __restrict__ pos)
{
    int j = (c << 5) + lane;
    if (j >= n) return 0xFFFFFFFFFFFFFFFFull;
    float xj = __ldg(pos + 3 * j);
    float yj = __ldg(pos + 3 * j + 1);
    float zj = __ldg(pos + 3 * j + 2);
    // Reference's gram-matrix expansion (numerical parity with the JAX code):
    float sqnj = xj * xj + yj * yj + zj * zj;
    float dt   = xi * xj + yi * yj + zi * zj;
    float sq   = sqni + sqnj - 2.0f * dt;
    sq = fmaxf(sq, 0.0f);
    float d = (sq > 0.0f) ? sqrtf(sq) : 0.0f;
    bool masked = (j == i) | (j < ms) | (j >= me) | (d > CUTOFF);
    float v = masked ? CUTOFF : d;
    return ((unsigned long long)__float_as_uint(v) << 32) | (unsigned int)j;
}

// One warp per row i. Exactness of the pruning:
//   - If ms >= 32: candidates j=0..31 are all cross-batch masked, so the true
//     array's entries there are exactly (10.0, 0..31) — seed held with that
//     (pre-sorted, zero work). Held max <= (10.0, 31), so any masked key
//     (10.0, j>=32) — including boundary-chunk masked entries — can never
//     enter the top-32. Only chunks overlapping [ms, me) need processing.
//   - If ms < 32: process chunk 0 exactly (real masks), same argument after.
__global__ void __launch_bounds__(256)
knn_kernel(const float* __restrict__ pos, const int* __restrict__ batch,
           float* __restrict__ out, int n)
{
    int warp = (blockIdx.x * blockDim.x + threadIdx.x) >> 5;
    int lane = threadIdx.x & 31;
    if (warp >= n) return;
    int i = warp;

    float xi = __ldg(pos + 3 * i);
    float yi = __ldg(pos + 3 * i + 1);
    float zi = __ldg(pos + 3 * i + 2);
    int   bi = __ldg(batch + i);
    float sqni = xi * xi + yi * yi + zi * zi;

    // Fused molecule-range lookup: warp-parallel binary search on sorted batch.
    // Even lanes run lower_bound(bi), odd lanes upper_bound(bi); 13 iterations.
    {
        int lo = 0, hi = n;
        bool upper = (lane & 1);
        while (lo < hi) {
            int mid = (lo + hi) >> 1;
            int v = __ldg(batch + mid);
            bool go = upper ? (v <= bi) : (v < bi);
            if (go) lo = mid + 1; else hi = mid;
        }
        int r = lo;
        int ms_ = __shfl_sync(0xffffffffu, r, 0);
        int me_ = __shfl_sync(0xffffffffu, r, 1);
        // fallthrough via registers
        // (kept in scope below)
        // ---- main selection ----
        unsigned long long held;
        if (ms_ < 32) {
            held = chunk_key(0, lane, n, i, ms_, me_, xi, yi, zi, sqni, pos);
            held = bitonic_sort32<true>(held, lane);
        } else {
            held = ((unsigned long long)__float_as_uint(CUTOFF) << 32) | (unsigned int)lane;
        }

        int cs = ms_ >> 5;
        if (cs < 1) cs = 1;           // chunk 0 already handled (or all-masked)
        int cend = (me_ - 1) >> 5;
        for (int c = cs; c <= cend; ++c) {
            unsigned long long cand = chunk_key(c, lane, n, i, ms_, me_, xi, yi, zi, sqni, pos);
            cand = bitonic_sort32<false>(cand, lane);   // descending: skip reverse in merge
            held = merge_keep32(held, cand, lane);
        }

        // Output: [edge_index[0] (N*K), edge_index[1] (N*K), edge_weight (N*K)]
        unsigned int nb = (unsigned int)(held & 0xffffffffu);
        float w = __uint_as_float((unsigned int)(held >> 32));
        int NK = n * KNN_K;
        int base = i * KNN_K + lane;
        out[base]          = (float)nb;   // neighbor index
        out[NK + base]     = (float)i;    // source row
        out[2 * NK + base] = w;           // distance weight
    }
}

extern "C" void kernel_launch(void* const* d_in, const int* in_sizes, int n_in,
                              void* d_out, int out_size)
{
    const float* pos   = (const float*)d_in[0];
    const int*   batch = (const int*)d_in[1];
    float*       out   = (float*)d_out;
    int n = in_sizes[1];  // batch has N elements

    int threads = 256;                       // 8 warps/block, 1 warp per row
    int blocks  = (n * 32 + threads - 1) / threads;
    knn_kernel<<<blocks, threads>>>(pos, batch, out, n);
}

// round 9
// speedup vs baseline: 1.5937x; 1.1679x over previous
#include <cuda_runtime.h>

#define KNN_K 32
#define CUTOFF_SQ 100.0f   // cutoff=10.0; sort in squared space, sqrt once at output

typedef unsigned long long u64;

// Conditional-take compare-exchange. Equal u64 keys are identical entries
// (key embeds the index), so either choice is correct on ties.
__device__ __forceinline__ void ce_swap(u64& key, u64 other, bool keep_min) {
    bool take = (other < key) == keep_min;
    if (take) key = other;
}

// Full 32-lane bitonic sort. ASC=true: lane l holds l-th smallest.
template <bool ASC>
__device__ __forceinline__ u64 bitonic_sort32(u64 key, int lane) {
    #pragma unroll
    for (int k = 2; k <= 32; k <<= 1) {
        #pragma unroll
        for (int j = k >> 1; j >= 1; j >>= 1) {
            u64 other = __shfl_xor_sync(0xffffffffu, key, j);
            bool keep_min = (((lane & k) == 0) == ((lane & j) == 0));
            if (!ASC) keep_min = !keep_min;
            ce_swap(key, other, keep_min);
        }
    }
    return key;
}

// held sorted asc, cand sorted DESC: elementwise min is a bitonic sequence
// containing exactly the 32 smallest of the 64; 5-stage merge re-sorts asc.
__device__ __forceinline__ u64 merge_keep32(u64 held, u64 cand_desc, int lane) {
    u64 lo = (held < cand_desc) ? held : cand_desc;
    #pragma unroll
    for (int j = 16; j >= 1; j >>= 1) {
        u64 other = __shfl_xor_sync(0xffffffffu, lo, j);
        ce_swap(lo, other, (lane & j) == 0);
    }
    return lo;
}

// Key for candidate j = c*32+lane: (float_bits(masked_sq) << 32) | j.
// sq >= 0 so float bits are u32-monotone; u64 compare == (sq asc, idx asc).
// Equivalence with the reference's (d asc, idx asc): sqrt is monotone and
// sqrt_rn(100)=10 exactly; masked entries carry value 100.0 and their real
// index, which tie-breaks identically to the reference's (10.0, j) entries.
__device__ __forceinline__ u64 chunk_key(
    int c, int lane, int n, int i, int ms, int me,
    float xi, float yi, float zi, float sqni, const float* __restrict__ pos)
{
    int j = (c << 5) + lane;
    if (j >= n) return 0xFFFFFFFFFFFFFFFFull;
    float xj = __ldg(pos + 3 * j);
    float yj = __ldg(pos + 3 * j + 1);
    float zj = __ldg(pos + 3 * j + 2);
    // Reference's gram-matrix expansion (numerical parity):
    float sqnj = xj * xj + yj * yj + zj * zj;
    float dt   = xi * xj + yi * yj + zi * zj;
    float sq   = sqni + sqnj - 2.0f * dt;
    sq = fmaxf(sq, 0.0f);
    bool masked = (j == i) | (j < ms) | (j >= me) | (sq > CUTOFF_SQ);
    float v = masked ? CUTOFF_SQ : sq;
    return ((u64)__float_as_uint(v) << 32) | (unsigned)j;
}

// Fallback: warp binary search (even lanes lower_bound, odd lanes upper_bound).
__device__ __forceinline__ void mol_bounds_bsearch(
    const int* __restrict__ batch, int n, int bi, int lane, int& ms, int& me)
{
    int lo = 0, hi = n;
    bool upper = (lane & 1);
    while (lo < hi) {
        int mid = (lo + hi) >> 1;
        int v = __ldg(batch + mid);
        bool go = upper ? (v <= bi) : (v < bi);
        if (go) lo = mid + 1; else hi = mid;
    }
    ms = __shfl_sync(0xffffffffu, lo, 0);
    me = __shfl_sync(0xffffffffu, lo, 1);
}

// One warp per row i. Pruning exactness: if ms>=32, candidates j=0..31 are all
// cross-batch masked, so the true entries there are exactly (100.0, 0..31) —
// seed held with that constant. Held max <= (100.0, 31), so any masked key
// (100.0, j>=32) can never enter the top-32; only chunks overlapping [ms,me)
// need processing. If ms<32, process chunk 0 with real masks first.
__global__ void __launch_bounds__(256)
knn_kernel(const float* __restrict__ pos, const int* __restrict__ batch,
           float* __restrict__ out, int n)
{
    int warp = (blockIdx.x * blockDim.x + threadIdx.x) >> 5;
    int lane = threadIdx.x & 31;
    if (warp >= n) return;
    int i = warp;

    float xi = __ldg(pos + 3 * i);
    float yi = __ldg(pos + 3 * i + 1);
    float zi = __ldg(pos + 3 * i + 2);
    int   bi = __ldg(batch + i);
    float sqni = xi * xi + yi * yi + zi * zi;

    // ---- molecule bounds: 2-probe warp-cooperative search around i ----
    // batch is sorted and batch[i]==bi, so the molecule's range surrounds i.
    int ms, me;
    {
        // Phase A: stride-16 probes covering [i-256, i+240].
        int p = i + (lane - 16) * 16;
        bool inb = (p >= 0) && (p < n);
        bool eq  = inb && (__ldg(batch + p) == bi);
        unsigned m = __ballot_sync(0xffffffffu, eq);
        unsigned low_ne = (~m) & 0xFFFFu;   // lanes 0..15 not-equal
        unsigned hi_ne  = (~m) >> 16;       // lanes 16..31 not-equal (lane16 = i, always eq)

        if (low_ne == 0u || hi_ne == 0u) {
            // molecule extends beyond the +-256 window (practically impossible
            // for this distribution) — exact fallback
            mol_bounds_bsearch(batch, n, bi, lane, ms, me);
        } else {
            int l_lo = 31 - __clz(low_ne);          // largest ne lane below 16
            int l_hi = 16 + (__ffs(hi_ne) - 1);     // smallest ne lane above 16
            int lo_base = i + (l_lo - 16) * 16 + 1; // ms in [lo_base, lo_base+15]
            int hi_end  = i + (l_hi - 16) * 16;     // me in (hi_end-16, hi_end]

            // Phase B: low lanes resolve ms, high lanes resolve me. One probe each.
            int q;
            bool eq2;
            if (lane < 16) {
                q = lo_base + lane;                 // q <= i, may be < 0
                eq2 = (q >= 0) && (__ldg(batch + q) == bi);
            } else {
                q = hi_end - 31 + lane;             // q in [hi_end-15, hi_end], >= i+1
                eq2 = (q < n) && (__ldg(batch + q) == bi);
            }
            unsigned m2 = __ballot_sync(0xffffffffu, eq2);
            unsigned lom = m2 & 0xFFFFu;            // nonzero (bit15 = q at p_{l_lo+1})
            unsigned him = m2 >> 16;                // may be zero
            ms = lo_base + (__ffs(lom) - 1);        // first eq index
            me = hi_end - 15 + (32 - __clz(him));   // one past last eq index
        }
    }

    // ---- selection ----
    u64 held;
    int c0;
    if (ms < 32) {
        u64 seed = chunk_key(0, lane, n, i, ms, me, xi, yi, zi, sqni, pos);
        held = bitonic_sort32<true>(seed, lane);
        c0 = 1;
    } else {
        held = ((u64)__float_as_uint(CUTOFF_SQ) << 32) | (unsigned)lane;
        c0 = ms >> 5;
    }
    int cend = (me - 1) >> 5;

    if (c0 <= cend) {
        // software-pipelined: issue next chunk's loads before sorting current
        u64 cand = chunk_key(c0, lane, n, i, ms, me, xi, yi, zi, sqni, pos);
        for (int c = c0;;) {
            int cn = c + 1;
            bool more = (cn <= cend);
            u64 next = 0;
            if (more) next = chunk_key(cn, lane, n, i, ms, me, xi, yi, zi, sqni, pos);
            cand = bitonic_sort32<false>(cand, lane);   // descending: no reverse in merge
            held = merge_keep32(held, cand, lane);
            if (!more) break;
            cand = next;
            c = cn;
        }
    }

    // Output: [edge_index[0] (N*K), edge_index[1] (N*K), edge_weight (N*K)]
    unsigned int nb = (unsigned int)(held & 0xffffffffu);
    float sqv = __uint_as_float((unsigned int)(held >> 32));
    float w = sqrtf(sqv);                  // sqrt(100)=10 exactly for fills/masked
    int NK = n * KNN_K;
    int base = i * KNN_K + lane;
    out[base]          = (float)nb;        // neighbor index
    out[NK + base]     = (float)i;         // source row
    out[2 * NK + base] = w;                // distance weight
}

extern "C" void kernel_launch(void* const* d_in, const int* in_sizes, int n_in,
                              void* d_out, int out_size)
{
    const float* pos   = (const float*)d_in[0];
    const int*   batch = (const int*)d_in[1];
    float*       out   = (float*)d_out;
    int n = in_sizes[1];  // batch has N elements

    int threads = 256;                       // 8 warps/block, 1 warp per row
    int blocks  = (n * 32 + threads - 1) / threads;
    knn_kernel<<<blocks, threads>>>(pos, batch, out, n);
}